// round 1
// baseline (speedup 1.0000x reference)
#include <cuda_runtime.h>
#include <math.h>

#define HH 160
#define WW 192
#define DD 160
#define NSZ (HH*WW*DD)          // 4,915,200
#define N3  (3*NSZ)             // 14,745,600

// ---- scratch (device globals; no allocations allowed) ----
static __device__ float  d_flowA[N3];
static __device__ float  d_flowB[N3];
static __device__ float  d_m[N3];
static __device__ float  d_v[N3];
static __device__ float  d_vh[N3];
static __device__ float  d_A[N3];     // ping buffer, 3 fields of NSZ
static __device__ float  d_Bf[N3];    // pong buffer, 3 fields of NSZ
static __device__ float  d_J[2*NSZ];  // S_J, S_JJ (precomputed from y)
static __device__ double d_part[1024];

#define WSF  729.0f
#define INVN (1.0f/4915200.0f)
// reg-gradient coefficients: 2 / (3 * 3*(L-1)*other*other)
#define CH_ (2.0f/43960320.0f)  // 9*159*192*160
#define CW_ (2.0f/44006400.0f)  // 9*160*191*160
#define CD_ (2.0f/43960320.0f)  // 9*160*192*159

// ---------------------------------------------------------------------------
// trilinear corner fetch (zero outside, matches jax map_coordinates order=1
// mode='constant' cval=0)
// ---------------------------------------------------------------------------
__device__ __forceinline__ void corners(const float* __restrict__ xv,
    float c0, float c1, float c2,
    float v[2][2][2], float& f0, float& f1, float& f2)
{
    float l0 = floorf(c0), l1 = floorf(c1), l2 = floorf(c2);
    int i0 = (int)l0, j0 = (int)l1, k0 = (int)l2;
    f0 = c0 - l0; f1 = c1 - l1; f2 = c2 - l2;
#pragma unroll
    for (int a = 0; a < 2; a++) {
        int ii = i0 + a; bool oa = (ii >= 0 && ii < HH);
#pragma unroll
        for (int b = 0; b < 2; b++) {
            int jj = j0 + b; bool ob = oa && (jj >= 0 && jj < WW);
            int base = (ii * WW + jj) * DD;
#pragma unroll
            for (int c = 0; c < 2; c++) {
                int kk = k0 + c; bool oc = ob && (kk >= 0 && kk < DD);
                v[a][b][c] = oc ? __ldg(&xv[base + kk]) : 0.f;
            }
        }
    }
}

// ---------------------------------------------------------------------------
// init: flowA = initial_flow; m = v = vhat = 0
// ---------------------------------------------------------------------------
__global__ void k_init(const float* __restrict__ init)
{
    int e = blockIdx.x * 256 + threadIdx.x;
    if (e < N3) {
        d_flowA[e] = init[e];
        d_m[e] = 0.f; d_v[e] = 0.f; d_vh[e] = 0.f;
    }
}

// ---------------------------------------------------------------------------
// D-axis box (win=9, zero pad), fused with warp + products:
//   fields: Iw, Iw*Iw, Iw*y  ->  d_A[0..2]
// one block per (i,j) line, DD threads
// ---------------------------------------------------------------------------
__global__ void k_boxd_fwd(const float* __restrict__ x, const float* __restrict__ y,
                           int flip)
{
    const float* fl = flip ? d_flowB : d_flowA;
    int line = blockIdx.x;
    int i = line / WW, j = line % WW;
    int k = threadIdx.x;
    int p = line * DD + k;

    float c0 = (float)i + fl[p];
    float c1 = (float)j + fl[NSZ + p];
    float c2 = (float)k + fl[2 * NSZ + p];
    float v[2][2][2]; float f0, f1, f2;
    corners(x, c0, c1, c2, v, f0, f1, f2);
    float u00 = v[0][0][0] * (1.f - f2) + v[0][0][1] * f2;
    float u01 = v[0][1][0] * (1.f - f2) + v[0][1][1] * f2;
    float u10 = v[1][0][0] * (1.f - f2) + v[1][0][1] * f2;
    float u11 = v[1][1][0] * (1.f - f2) + v[1][1][1] * f2;
    float t0 = u00 * (1.f - f1) + u01 * f1;
    float t1 = u10 * (1.f - f1) + u11 * f1;
    float Iw = t0 * (1.f - f0) + t1 * f0;
    float yy = y[p];

    __shared__ float s[3][DD + 8];
    s[0][4 + k] = Iw;
    s[1][4 + k] = Iw * Iw;
    s[2][4 + k] = Iw * yy;
    if (k < 4) {
        s[0][k] = 0.f; s[1][k] = 0.f; s[2][k] = 0.f;
        s[0][DD + 4 + k] = 0.f; s[1][DD + 4 + k] = 0.f; s[2][DD + 4 + k] = 0.f;
    }
    __syncthreads();
    float r0 = 0.f, r1 = 0.f, r2 = 0.f;
#pragma unroll
    for (int t = 0; t < 9; t++) {
        r0 += s[0][k + t]; r1 += s[1][k + t]; r2 += s[2][k + t];
    }
    d_A[p] = r0; d_A[NSZ + p] = r1; d_A[2 * NSZ + p] = r2;
}

// D-axis box of (y, y*y) -> d_A[0..1]   (precompute for S_J, S_JJ)
__global__ void k_boxd_pre(const float* __restrict__ y)
{
    int line = blockIdx.x;
    int k = threadIdx.x;
    int p = line * DD + k;
    float yy = y[p];
    __shared__ float s[2][DD + 8];
    s[0][4 + k] = yy; s[1][4 + k] = yy * yy;
    if (k < 4) {
        s[0][k] = 0.f; s[1][k] = 0.f;
        s[0][DD + 4 + k] = 0.f; s[1][DD + 4 + k] = 0.f;
    }
    __syncthreads();
    float r0 = 0.f, r1 = 0.f;
#pragma unroll
    for (int t = 0; t < 9; t++) { r0 += s[0][k + t]; r1 += s[1][k + t]; }
    d_A[p] = r0; d_A[NSZ + p] = r1;
}

// D-axis box, generic 3 fields: d_Bf -> d_A
__global__ void k_boxd_gen(void)
{
    int line = blockIdx.x;
    int k = threadIdx.x;
    int p = line * DD + k;
    __shared__ float s[3][DD + 8];
    s[0][4 + k] = d_Bf[p];
    s[1][4 + k] = d_Bf[NSZ + p];
    s[2][4 + k] = d_Bf[2 * NSZ + p];
    if (k < 4) {
        s[0][k] = 0.f; s[1][k] = 0.f; s[2][k] = 0.f;
        s[0][DD + 4 + k] = 0.f; s[1][DD + 4 + k] = 0.f; s[2][DD + 4 + k] = 0.f;
    }
    __syncthreads();
    float r0 = 0.f, r1 = 0.f, r2 = 0.f;
#pragma unroll
    for (int t = 0; t < 9; t++) {
        r0 += s[0][k + t]; r1 += s[1][k + t]; r2 += s[2][k + t];
    }
    d_A[p] = r0; d_A[NSZ + p] = r1; d_A[2 * NSZ + p] = r2;
}

// ---------------------------------------------------------------------------
// strided-axis box pass (W axis: S=DD,L=WW,hi=HH ; H axis: S=WW*DD,L=HH,hi=1)
// dir: 0 = A->Bf, 1 = Bf->A, 2 = Bf->J
// block (32 lo, 32 axis-outputs), smem tile 40 rows with halo
// ---------------------------------------------------------------------------
__global__ void k_boxp(int dir, int nf, int L, int S)
{
    const float* in  = (dir == 0) ? d_A  : d_Bf;
    float*       out = (dir == 0) ? d_Bf : ((dir == 1) ? d_A : d_J);
    __shared__ float sm[3][40][32];
    int lo = blockIdx.x * 32 + threadIdx.x;
    int ac = blockIdx.y * 32;
    int hibase = blockIdx.z * L * S;

    for (int r = threadIdx.y; r < 40; r += 32) {
        int a = ac + r - 4;
        bool ok = (a >= 0 && a < L);
        int idx = hibase + a * S + lo;
        for (int f = 0; f < nf; f++)
            sm[f][r][threadIdx.x] = ok ? in[f * NSZ + idx] : 0.f;
    }
    __syncthreads();
    int a = ac + threadIdx.y;
    if (a < L) {
        int idx = hibase + a * S + lo;
        for (int f = 0; f < nf; f++) {
            float s = 0.f;
#pragma unroll
            for (int t = 0; t < 9; t++) s += sm[f][threadIdx.y + t][threadIdx.x];
            out[f * NSZ + idx] = s;
        }
    }
}

// ---------------------------------------------------------------------------
// NCC partial-derivative fields:  d_A(S_I,S_II,S_IJ), d_J(S_J,S_JJ) -> d_Bf(gI,gII,gIJ)
// ---------------------------------------------------------------------------
__global__ void k_gf(void)
{
    int p = blockIdx.x * 256 + threadIdx.x;
    if (p >= NSZ) return;
    float SI  = d_A[p], SII = d_A[NSZ + p], SIJ = d_A[2 * NSZ + p];
    float SJ  = d_J[p], SJJ = d_J[NSZ + p];
    float uI = SI / WSF, uJ = SJ / WSF;
    float cross = SIJ - uJ * SI - uI * SJ + uI * uJ * WSF;
    float Iv = SII - 2.f * uI * SI + uI * uI * WSF;
    float Jv = SJJ - 2.f * uJ * SJ + uJ * uJ * WSF;
    float Dn = Iv * Jv + 1e-5f;
    float t0 = cross / Dn;
    float q  = 2.f * t0;          // dcc/dS_IJ
    float r  = t0 * t0 * Jv;      // cross^2 * Jv / Dn^2
    d_Bf[p]           = -q * uJ + 2.f * r * uI;  // dcc/dS_I
    d_Bf[NSZ + p]     = -r;                      // dcc/dS_II
    d_Bf[2 * NSZ + p] = q;                       // dcc/dS_IJ
}

// ---------------------------------------------------------------------------
// chain rule (NCC grad wrt Iw -> wrt flow via trilerp jacobian) + reg grad
// + fused Adam(amsgrad) update, writing the ping-pong flow buffer
// d_A holds box(gI), box(gII), box(gIJ)
// ---------------------------------------------------------------------------
__global__ void k_chain_adam(const float* __restrict__ x, const float* __restrict__ y,
                             int flip, float bc1, float sbc2)
{
    const float* fc_ = flip ? d_flowB : d_flowA;
    float*       fn_ = flip ? d_flowA : d_flowB;
    int p = blockIdx.x * 256 + threadIdx.x;
    if (p >= NSZ) return;
    int k = p % DD; int t = p / DD; int j = t % WW; int i = t / WW;

    float f0 = fc_[p], f1 = fc_[NSZ + p], f2c = fc_[2 * NSZ + p];
    float c0 = (float)i + f0, c1 = (float)j + f1, c2 = (float)k + f2c;
    float v[2][2][2]; float fr0, fr1, fr2;
    corners(x, c0, c1, c2, v, fr0, fr1, fr2);
    float u00 = v[0][0][0] * (1.f - fr2) + v[0][0][1] * fr2;
    float u01 = v[0][1][0] * (1.f - fr2) + v[0][1][1] * fr2;
    float u10 = v[1][0][0] * (1.f - fr2) + v[1][0][1] * fr2;
    float u11 = v[1][1][0] * (1.f - fr2) + v[1][1][1] * fr2;
    float ta = u00 * (1.f - fr1) + u01 * fr1;
    float tb = u10 * (1.f - fr1) + u11 * fr1;
    float val = ta * (1.f - fr0) + tb * fr0;                 // Iw
    float gx0 = tb - ta;
    float gx1 = (1.f - fr0) * (u01 - u00) + fr0 * (u11 - u10);
    float d00 = v[0][0][1] - v[0][0][0], d01 = v[0][1][1] - v[0][1][0];
    float d10 = v[1][0][1] - v[1][0][0], d11 = v[1][1][1] - v[1][1][0];
    float gx2 = (1.f - fr0) * ((1.f - fr1) * d00 + fr1 * d01)
              + fr0 * ((1.f - fr1) * d10 + fr1 * d11);

    float dI = -INVN * (d_A[p] + 2.f * val * d_A[NSZ + p] + y[p] * d_A[2 * NSZ + p]);

    float gx[3]  = {gx0, gx1, gx2};
    float fcv[3] = {f0, f1, f2c};
#pragma unroll
    for (int ch = 0; ch < 3; ch++) {
        int e = ch * NSZ + p;
        float fcc = fcv[ch];
        float reg = 0.f;
        if (i > 0)      reg += CH_ * (fcc - fc_[e - WW * DD]);
        if (i < HH - 1) reg -= CH_ * (fc_[e + WW * DD] - fcc);
        if (j > 0)      reg += CW_ * (fcc - fc_[e - DD]);
        if (j < WW - 1) reg -= CW_ * (fc_[e + DD] - fcc);
        if (k > 0)      reg += CD_ * (fcc - fc_[e - 1]);
        if (k < DD - 1) reg -= CD_ * (fc_[e + 1] - fcc);
        float g = dI * gx[ch] + reg;

        float mm = 0.9f * d_m[e] + 0.1f * g;
        float vv = 0.999f * d_v[e] + 0.001f * g * g;
        float vh = fmaxf(d_vh[e], vv);
        d_m[e] = mm; d_v[e] = vv; d_vh[e] = vh;
        float denom = sqrtf(vh) / sbc2 + 1e-8f;
        fn_[e] = fcc - 0.1f * (mm / bc1) / denom;
    }
}

// ---------------------------------------------------------------------------
// deterministic reduction: mean((flow_final - initial_flow)^2)
// ---------------------------------------------------------------------------
__global__ void k_red1(const float* __restrict__ init)
{
    double acc = 0.0;
    for (int e = blockIdx.x * 256 + threadIdx.x; e < N3; e += 1024 * 256) {
        float d = d_flowB[e] - init[e];
        acc += (double)(d * d);
    }
    __shared__ double sd[256];
    sd[threadIdx.x] = acc; __syncthreads();
    for (int s = 128; s > 0; s >>= 1) {
        if (threadIdx.x < s) sd[threadIdx.x] += sd[threadIdx.x + s];
        __syncthreads();
    }
    if (threadIdx.x == 0) d_part[blockIdx.x] = sd[0];
}

__global__ void k_red2(float* __restrict__ out)
{
    __shared__ double sd[1024];
    sd[threadIdx.x] = d_part[threadIdx.x]; __syncthreads();
    for (int s = 512; s > 0; s >>= 1) {
        if (threadIdx.x < s) sd[threadIdx.x] += sd[threadIdx.x + s];
        __syncthreads();
    }
    if (threadIdx.x == 0) out[0] = (float)(sd[0] / (double)N3);
}

// ---------------------------------------------------------------------------
extern "C" void kernel_launch(void* const* d_in, const int* in_sizes, int n_in,
                              void* d_out, int out_size)
{
    (void)in_sizes; (void)n_in; (void)out_size;
    const float* x    = (const float*)d_in[0];
    const float* y    = (const float*)d_in[1];
    const float* init = (const float*)d_in[2];
    float* out = (float*)d_out;

    dim3 tb2(32, 32);
    dim3 gW(DD / 32, WW / 32, HH);        // W-axis pass
    dim3 gH((WW * DD) / 32, HH / 32, 1);  // H-axis pass

    k_init<<<N3 / 256, 256>>>(init);

    // precompute S_J, S_JJ
    k_boxd_pre<<<HH * WW, DD>>>(y);
    k_boxp<<<gW, tb2>>>(0, 2, WW, DD);
    k_boxp<<<gH, tb2>>>(2, 2, HH, WW * DD);

    for (int t = 1; t <= 5; t++) {
        int flip = (t - 1) & 1;
        float bc1  = (float)(1.0 - pow(0.9, (double)t));
        float sbc2 = sqrtf((float)(1.0 - pow(0.999, (double)t)));

        // forward window sums of Iw, Iw^2, Iw*y
        k_boxd_fwd<<<HH * WW, DD>>>(x, y, flip);
        k_boxp<<<gW, tb2>>>(0, 3, WW, DD);
        k_boxp<<<gH, tb2>>>(1, 3, HH, WW * DD);
        // per-voxel partials of cc wrt the sums
        k_gf<<<NSZ / 256, 256>>>();
        // adjoint (same) box filter on the partials
        k_boxd_gen<<<HH * WW, DD>>>();
        k_boxp<<<gW, tb2>>>(0, 3, WW, DD);
        k_boxp<<<gH, tb2>>>(1, 3, HH, WW * DD);
        // chain rule + reg grad + Adam
        k_chain_adam<<<NSZ / 256, 256>>>(x, y, flip, bc1, sbc2);
    }

    k_red1<<<1024, 256>>>(init);
    k_red2<<<1, 1024>>>(out);
}

// round 2
// speedup vs baseline: 1.3755x; 1.3755x over previous
#include <cuda_runtime.h>
#include <math.h>

#define HH 160
#define WW 192
#define DD 160
#define NSZ (HH*WW*DD)          // 4,915,200
#define N3  (3*NSZ)             // 14,745,600
#define CHUNK 16

// ---- scratch (device globals; no allocations allowed) ----
static __device__ float  d_flowA[N3];
static __device__ float  d_flowB[N3];
static __device__ float  d_m[N3];
static __device__ float  d_v[N3];
static __device__ float  d_vh[N3];
static __device__ float  d_A[N3];     // ping buffer, 3 fields of NSZ
static __device__ float  d_Bf[N3];    // pong buffer, 3 fields of NSZ
static __device__ float  d_J[2*NSZ];  // S_J, S_JJ (precomputed from y)
static __device__ double d_part[1024];

#define WSF  729.0f
#define INVN (1.0f/4915200.0f)
// reg-gradient coefficients: 2 / (3 * 3*(L-1)*other*other)
#define CH_ (2.0f/43960320.0f)  // 9*159*192*160
#define CW_ (2.0f/44006400.0f)  // 9*160*191*160
#define CD_ (2.0f/43960320.0f)  // 9*160*192*159

__device__ __forceinline__ float4 f4z() { return make_float4(0.f, 0.f, 0.f, 0.f); }
__device__ __forceinline__ float4 operator+(float4 a, float4 b) {
    return make_float4(a.x + b.x, a.y + b.y, a.z + b.z, a.w + b.w);
}
__device__ __forceinline__ float4 operator-(float4 a, float4 b) {
    return make_float4(a.x - b.x, a.y - b.y, a.z - b.z, a.w - b.w);
}

__device__ __forceinline__ float* bufsel(int s)
{
    return (s == 0) ? d_A : ((s == 1) ? d_Bf : d_J);
}

// ---------------------------------------------------------------------------
// trilinear corner fetch (zero outside, matches jax map_coordinates order=1
// mode='constant' cval=0)
// ---------------------------------------------------------------------------
__device__ __forceinline__ void corners(const float* __restrict__ xv,
    float c0, float c1, float c2,
    float v[2][2][2], float& f0, float& f1, float& f2)
{
    float l0 = floorf(c0), l1 = floorf(c1), l2 = floorf(c2);
    int i0 = (int)l0, j0 = (int)l1, k0 = (int)l2;
    f0 = c0 - l0; f1 = c1 - l1; f2 = c2 - l2;
#pragma unroll
    for (int a = 0; a < 2; a++) {
        int ii = i0 + a; bool oa = (ii >= 0 && ii < HH);
#pragma unroll
        for (int b = 0; b < 2; b++) {
            int jj = j0 + b; bool ob = oa && (jj >= 0 && jj < WW);
            int base = (ii * WW + jj) * DD;
#pragma unroll
            for (int c = 0; c < 2; c++) {
                int kk = k0 + c; bool oc = ob && (kk >= 0 && kk < DD);
                v[a][b][c] = oc ? __ldg(&xv[base + kk]) : 0.f;
            }
        }
    }
}

// ---------------------------------------------------------------------------
__global__ void k_init(const float* __restrict__ init)
{
    int e = blockIdx.x * 256 + threadIdx.x;
    if (e < N3) {
        d_flowA[e] = init[e];
        d_m[e] = 0.f; d_v[e] = 0.f; d_vh[e] = 0.f;
    }
}

// ---------------------------------------------------------------------------
// D-axis box (win=9, zero pad), fused with warp + products:
//   fields: Iw, Iw*Iw, Iw*y  ->  d_A[0..2]
// ---------------------------------------------------------------------------
__global__ void k_boxd_fwd(const float* __restrict__ x, const float* __restrict__ y,
                           int flip)
{
    const float* fl = flip ? d_flowB : d_flowA;
    int line = blockIdx.x;
    int i = line / WW, j = line % WW;
    int k = threadIdx.x;
    int p = line * DD + k;

    float c0 = (float)i + fl[p];
    float c1 = (float)j + fl[NSZ + p];
    float c2 = (float)k + fl[2 * NSZ + p];
    float v[2][2][2]; float f0, f1, f2;
    corners(x, c0, c1, c2, v, f0, f1, f2);
    float u00 = v[0][0][0] * (1.f - f2) + v[0][0][1] * f2;
    float u01 = v[0][1][0] * (1.f - f2) + v[0][1][1] * f2;
    float u10 = v[1][0][0] * (1.f - f2) + v[1][0][1] * f2;
    float u11 = v[1][1][0] * (1.f - f2) + v[1][1][1] * f2;
    float t0 = u00 * (1.f - f1) + u01 * f1;
    float t1 = u10 * (1.f - f1) + u11 * f1;
    float Iw = t0 * (1.f - f0) + t1 * f0;
    float yy = y[p];

    __shared__ float s[3][DD + 8];
    s[0][4 + k] = Iw;
    s[1][4 + k] = Iw * Iw;
    s[2][4 + k] = Iw * yy;
    if (k < 4) {
        s[0][k] = 0.f; s[1][k] = 0.f; s[2][k] = 0.f;
        s[0][DD + 4 + k] = 0.f; s[1][DD + 4 + k] = 0.f; s[2][DD + 4 + k] = 0.f;
    }
    __syncthreads();
    float r0 = 0.f, r1 = 0.f, r2 = 0.f;
#pragma unroll
    for (int t = 0; t < 9; t++) {
        r0 += s[0][k + t]; r1 += s[1][k + t]; r2 += s[2][k + t];
    }
    d_A[p] = r0; d_A[NSZ + p] = r1; d_A[2 * NSZ + p] = r2;
}

// D-axis box of (y, y*y) -> d_A[0..1]   (precompute for S_J, S_JJ)
__global__ void k_boxd_pre(const float* __restrict__ y)
{
    int line = blockIdx.x;
    int k = threadIdx.x;
    int p = line * DD + k;
    float yy = y[p];
    __shared__ float s[2][DD + 8];
    s[0][4 + k] = yy; s[1][4 + k] = yy * yy;
    if (k < 4) {
        s[0][k] = 0.f; s[1][k] = 0.f;
        s[0][DD + 4 + k] = 0.f; s[1][DD + 4 + k] = 0.f;
    }
    __syncthreads();
    float r0 = 0.f, r1 = 0.f;
#pragma unroll
    for (int t = 0; t < 9; t++) { r0 += s[0][k + t]; r1 += s[1][k + t]; }
    d_A[p] = r0; d_A[NSZ + p] = r1;
}

// ---------------------------------------------------------------------------
// Fused: NCC partials wrt window sums + D-axis box of the partials.
// in: d_A = S_I, S_II, S_IJ ; d_J = S_J, S_JJ   out: d_Bf = boxD(gI,gII,gIJ)
// ---------------------------------------------------------------------------
__global__ void k_gf_boxd(void)
{
    int line = blockIdx.x;
    int k = threadIdx.x;
    int p = line * DD + k;

    float SI  = d_A[p], SII = d_A[NSZ + p], SIJ = d_A[2 * NSZ + p];
    float SJ  = d_J[p], SJJ = d_J[NSZ + p];
    float uI = SI / WSF, uJ = SJ / WSF;
    float cross = SIJ - uJ * SI - uI * SJ + uI * uJ * WSF;
    float Iv = SII - 2.f * uI * SI + uI * uI * WSF;
    float Jv = SJJ - 2.f * uJ * SJ + uJ * uJ * WSF;
    float Dn = Iv * Jv + 1e-5f;
    float t0 = cross / Dn;
    float q  = 2.f * t0;          // dcc/dS_IJ
    float r  = t0 * t0 * Jv;      // cross^2 * Jv / Dn^2
    float gI  = -q * uJ + 2.f * r * uI;
    float gII = -r;
    float gIJ = q;

    __shared__ float s[3][DD + 8];
    s[0][4 + k] = gI; s[1][4 + k] = gII; s[2][4 + k] = gIJ;
    if (k < 4) {
        s[0][k] = 0.f; s[1][k] = 0.f; s[2][k] = 0.f;
        s[0][DD + 4 + k] = 0.f; s[1][DD + 4 + k] = 0.f; s[2][DD + 4 + k] = 0.f;
    }
    __syncthreads();
    float r0 = 0.f, r1 = 0.f, r2 = 0.f;
#pragma unroll
    for (int t = 0; t < 9; t++) {
        r0 += s[0][k + t]; r1 += s[1][k + t]; r2 += s[2][k + t];
    }
    d_Bf[p] = r0; d_Bf[NSZ + p] = r1; d_Bf[2 * NSZ + p] = r2;
}

// ---------------------------------------------------------------------------
// Strided-axis box via register sliding window, float4 across lo dimension.
// Each thread produces CHUNK outputs along the filtered axis.
//   s += in[a+4] - in[a-5]   (zero outside [0,L))
// W axis: L=WW, S=DD,    nlo4=DD/4,        nchunk=WW/CHUNK, hi=HH
// H axis: L=HH, S=WW*DD, nlo4=(WW*DD)/4,   nchunk=HH/CHUNK, hi=1
// ---------------------------------------------------------------------------
template<int NF>
__global__ void k_boxs(int ssel, int dsel, int L, int S, int nlo4, int nchunk,
                       int total)
{
    int tid = blockIdx.x * 256 + threadIdx.x;
    if (tid >= total) return;
    int lo4 = tid % nlo4;
    int rest = tid / nlo4;
    int chunk = rest % nchunk;
    int hi = rest / nchunk;

    const float* __restrict__ in = bufsel(ssel);
    float* __restrict__ out = bufsel(dsel);

    int c0 = chunk * CHUNK;
    int base = hi * L * S + lo4 * 4;

    float4 s[NF];
#pragma unroll
    for (int f = 0; f < NF; f++) s[f] = f4z();

    // initial 9-tap window centered at c0
#pragma unroll
    for (int t = -4; t <= 4; t++) {
        int a = c0 + t;
        if ((unsigned)a < (unsigned)L) {
#pragma unroll
            for (int f = 0; f < NF; f++)
                s[f] = s[f] + *(const float4*)(in + f * NSZ + base + a * S);
        }
    }
#pragma unroll
    for (int f = 0; f < NF; f++)
        *(float4*)(out + f * NSZ + base + c0 * S) = s[f];

#pragma unroll
    for (int o = 1; o < CHUNK; o++) {
        int a = c0 + o;
        int ain = a + 4, aout = a - 5;
        bool bi = ((unsigned)ain < (unsigned)L);
        bool bo = (aout >= 0);
#pragma unroll
        for (int f = 0; f < NF; f++) {
            float4 vin  = bi ? *(const float4*)(in + f * NSZ + base + ain * S)  : f4z();
            float4 vout = bo ? *(const float4*)(in + f * NSZ + base + aout * S) : f4z();
            s[f] = s[f] + vin - vout;
            *(float4*)(out + f * NSZ + base + a * S) = s[f];
        }
    }
}

// ---------------------------------------------------------------------------
// chain rule (NCC grad wrt Iw -> wrt flow via trilerp jacobian) + reg grad
// + fused Adam(amsgrad) update.  box(g*) is in d_Bf.
// ---------------------------------------------------------------------------
__global__ void k_chain_adam(const float* __restrict__ x, const float* __restrict__ y,
                             int flip, float bc1, float sbc2)
{
    const float* fc_ = flip ? d_flowB : d_flowA;
    float*       fn_ = flip ? d_flowA : d_flowB;
    int p = blockIdx.x * 256 + threadIdx.x;
    if (p >= NSZ) return;
    int k = p % DD; int t = p / DD; int j = t % WW; int i = t / WW;

    float f0 = fc_[p], f1 = fc_[NSZ + p], f2c = fc_[2 * NSZ + p];
    float c0 = (float)i + f0, c1 = (float)j + f1, c2 = (float)k + f2c;
    float v[2][2][2]; float fr0, fr1, fr2;
    corners(x, c0, c1, c2, v, fr0, fr1, fr2);
    float u00 = v[0][0][0] * (1.f - fr2) + v[0][0][1] * fr2;
    float u01 = v[0][1][0] * (1.f - fr2) + v[0][1][1] * fr2;
    float u10 = v[1][0][0] * (1.f - fr2) + v[1][0][1] * fr2;
    float u11 = v[1][1][0] * (1.f - fr2) + v[1][1][1] * fr2;
    float ta = u00 * (1.f - fr1) + u01 * fr1;
    float tb = u10 * (1.f - fr1) + u11 * fr1;
    float val = ta * (1.f - fr0) + tb * fr0;                 // Iw
    float gx0 = tb - ta;
    float gx1 = (1.f - fr0) * (u01 - u00) + fr0 * (u11 - u10);
    float d00 = v[0][0][1] - v[0][0][0], d01 = v[0][1][1] - v[0][1][0];
    float d10 = v[1][0][1] - v[1][0][0], d11 = v[1][1][1] - v[1][1][0];
    float gx2 = (1.f - fr0) * ((1.f - fr1) * d00 + fr1 * d01)
              + fr0 * ((1.f - fr1) * d10 + fr1 * d11);

    float dI = -INVN * (d_Bf[p] + 2.f * val * d_Bf[NSZ + p] + y[p] * d_Bf[2 * NSZ + p]);

    float gx[3]  = {gx0, gx1, gx2};
    float fcv[3] = {f0, f1, f2c};
#pragma unroll
    for (int ch = 0; ch < 3; ch++) {
        int e = ch * NSZ + p;
        float fcc = fcv[ch];
        float reg = 0.f;
        if (i > 0)      reg += CH_ * (fcc - fc_[e - WW * DD]);
        if (i < HH - 1) reg -= CH_ * (fc_[e + WW * DD] - fcc);
        if (j > 0)      reg += CW_ * (fcc - fc_[e - DD]);
        if (j < WW - 1) reg -= CW_ * (fc_[e + DD] - fcc);
        if (k > 0)      reg += CD_ * (fcc - fc_[e - 1]);
        if (k < DD - 1) reg -= CD_ * (fc_[e + 1] - fcc);
        float g = dI * gx[ch] + reg;

        float mm = 0.9f * d_m[e] + 0.1f * g;
        float vv = 0.999f * d_v[e] + 0.001f * g * g;
        float vh = fmaxf(d_vh[e], vv);
        d_m[e] = mm; d_v[e] = vv; d_vh[e] = vh;
        float denom = sqrtf(vh) / sbc2 + 1e-8f;
        fn_[e] = fcc - 0.1f * (mm / bc1) / denom;
    }
}

// ---------------------------------------------------------------------------
// deterministic reduction: mean((flow_final - initial_flow)^2)
// ---------------------------------------------------------------------------
__global__ void k_red1(const float* __restrict__ init)
{
    double acc = 0.0;
    for (int e = blockIdx.x * 256 + threadIdx.x; e < N3; e += 1024 * 256) {
        float d = d_flowB[e] - init[e];
        acc += (double)(d * d);
    }
    __shared__ double sd[256];
    sd[threadIdx.x] = acc; __syncthreads();
    for (int s = 128; s > 0; s >>= 1) {
        if (threadIdx.x < s) sd[threadIdx.x] += sd[threadIdx.x + s];
        __syncthreads();
    }
    if (threadIdx.x == 0) d_part[blockIdx.x] = sd[0];
}

__global__ void k_red2(float* __restrict__ out)
{
    __shared__ double sd[1024];
    sd[threadIdx.x] = d_part[threadIdx.x]; __syncthreads();
    for (int s = 512; s > 0; s >>= 1) {
        if (threadIdx.x < s) sd[threadIdx.x] += sd[threadIdx.x + s];
        __syncthreads();
    }
    if (threadIdx.x == 0) out[0] = (float)(sd[0] / (double)N3);
}

// ---------------------------------------------------------------------------
extern "C" void kernel_launch(void* const* d_in, const int* in_sizes, int n_in,
                              void* d_out, int out_size)
{
    (void)in_sizes; (void)n_in; (void)out_size;
    const float* x    = (const float*)d_in[0];
    const float* y    = (const float*)d_in[1];
    const float* init = (const float*)d_in[2];
    float* out = (float*)d_out;

    // W-axis pass params: L=WW, S=DD, nlo4=DD/4, nchunk=WW/CHUNK
    const int W_L = WW, W_S = DD, W_nlo4 = DD / 4, W_nch = WW / CHUNK;
    const int W_total = W_nlo4 * W_nch * HH;          // 76800
    // H-axis pass params: L=HH, S=WW*DD, nlo4=(WW*DD)/4, nchunk=HH/CHUNK
    const int H_L = HH, H_S = WW * DD, H_nlo4 = (WW * DD) / 4, H_nch = HH / CHUNK;
    const int H_total = H_nlo4 * H_nch;               // 76800
    const int BOX_BLOCKS = (W_total + 255) / 256;     // 300

    k_init<<<N3 / 256, 256>>>(init);

    // precompute S_J, S_JJ: boxD -> boxW -> boxH into d_J
    k_boxd_pre<<<HH * WW, DD>>>(y);
    k_boxs<2><<<BOX_BLOCKS, 256>>>(0, 1, W_L, W_S, W_nlo4, W_nch, W_total);
    k_boxs<2><<<BOX_BLOCKS, 256>>>(1, 2, H_L, H_S, H_nlo4, H_nch, H_total);

    for (int t = 1; t <= 5; t++) {
        int flip = (t - 1) & 1;
        float bc1  = (float)(1.0 - pow(0.9, (double)t));
        float sbc2 = sqrtf((float)(1.0 - pow(0.999, (double)t)));

        // forward window sums of Iw, Iw^2, Iw*y : D (fused w/ warp), W, H
        k_boxd_fwd<<<HH * WW, DD>>>(x, y, flip);
        k_boxs<3><<<BOX_BLOCKS, 256>>>(0, 1, W_L, W_S, W_nlo4, W_nch, W_total); // A->Bf
        k_boxs<3><<<BOX_BLOCKS, 256>>>(1, 0, H_L, H_S, H_nlo4, H_nch, H_total); // Bf->A
        // partials of cc wrt sums, fused with adjoint D-box
        k_gf_boxd<<<HH * WW, DD>>>();                                           // A,J->Bf
        k_boxs<3><<<BOX_BLOCKS, 256>>>(1, 0, W_L, W_S, W_nlo4, W_nch, W_total); // Bf->A
        k_boxs<3><<<BOX_BLOCKS, 256>>>(0, 1, H_L, H_S, H_nlo4, H_nch, H_total); // A->Bf
        // chain rule + reg grad + Adam
        k_chain_adam<<<NSZ / 256, 256>>>(x, y, flip, bc1, sbc2);
    }

    k_red1<<<1024, 256>>>(init);
    k_red2<<<1, 1024>>>(out);
}

// round 3
// speedup vs baseline: 1.5025x; 1.0923x over previous
#include <cuda_runtime.h>
#include <math.h>

#define HH 160
#define WW 192
#define DD 160
#define NSZ (HH*WW*DD)          // 4,915,200
#define N3  (3*NSZ)             // 14,745,600
#define CHUNK 16
#define NBCHAIN (NSZ/256)       // 19200 chain blocks

// ---- scratch (device globals; no allocations allowed) ----
static __device__ float  d_flowA[N3];
static __device__ float  d_flowB[N3];
static __device__ float  d_m[N3];
static __device__ float  d_v[N3];
static __device__ float  d_vh[N3];
static __device__ float  d_A[N3];     // ping buffer, 3 fields of NSZ
static __device__ float  d_Bf[N3];    // pong buffer, 3 fields of NSZ
static __device__ float  d_J[2*NSZ];  // S_J, S_JJ (precomputed from y)
static __device__ double d_part[NBCHAIN];

#define WSF  729.0f
#define INVN (1.0f/4915200.0f)
// reg-gradient coefficients: 2 / (3 * 3*(L-1)*other*other)
#define CH_ (2.0f/43960320.0f)  // 9*159*192*160
#define CW_ (2.0f/44006400.0f)  // 9*160*191*160
#define CD_ (2.0f/43960320.0f)  // 9*160*192*159

__device__ __forceinline__ float4 f4z() { return make_float4(0.f, 0.f, 0.f, 0.f); }
__device__ __forceinline__ float4 operator+(float4 a, float4 b) {
    return make_float4(a.x + b.x, a.y + b.y, a.z + b.z, a.w + b.w);
}
__device__ __forceinline__ float4 operator-(float4 a, float4 b) {
    return make_float4(a.x - b.x, a.y - b.y, a.z - b.z, a.w - b.w);
}

__device__ __forceinline__ float* bufsel(int s)
{
    return (s == 0) ? d_A : ((s == 1) ? d_Bf : d_J);
}

// ---------------------------------------------------------------------------
// trilinear corner fetch (zero outside)
// ---------------------------------------------------------------------------
__device__ __forceinline__ void corners(const float* __restrict__ xv,
    float c0, float c1, float c2,
    float v[2][2][2], float& f0, float& f1, float& f2)
{
    float l0 = floorf(c0), l1 = floorf(c1), l2 = floorf(c2);
    int i0 = (int)l0, j0 = (int)l1, k0 = (int)l2;
    f0 = c0 - l0; f1 = c1 - l1; f2 = c2 - l2;
#pragma unroll
    for (int a = 0; a < 2; a++) {
        int ii = i0 + a; bool oa = (ii >= 0 && ii < HH);
#pragma unroll
        for (int b = 0; b < 2; b++) {
            int jj = j0 + b; bool ob = oa && (jj >= 0 && jj < WW);
            int base = (ii * WW + jj) * DD;
#pragma unroll
            for (int c = 0; c < 2; c++) {
                int kk = k0 + c; bool oc = ob && (kk >= 0 && kk < DD);
                v[a][b][c] = oc ? __ldg(&xv[base + kk]) : 0.f;
            }
        }
    }
}

// ---------------------------------------------------------------------------
__global__ void k_init(const float* __restrict__ init)
{
    int e = blockIdx.x * 256 + threadIdx.x;
    if (e < N3) {
        d_flowA[e] = init[e];
        d_m[e] = 0.f; d_v[e] = 0.f; d_vh[e] = 0.f;
    }
}

// ---------------------------------------------------------------------------
// D-axis box (win=9, zero pad), fused with warp + products -> d_A[0..2]
// ---------------------------------------------------------------------------
__global__ void k_boxd_fwd(const float* __restrict__ x, const float* __restrict__ y,
                           int flip)
{
    const float* fl = flip ? d_flowB : d_flowA;
    int line = blockIdx.x;
    int i = line / WW, j = line % WW;
    int k = threadIdx.x;
    int p = line * DD + k;

    float c0 = (float)i + fl[p];
    float c1 = (float)j + fl[NSZ + p];
    float c2 = (float)k + fl[2 * NSZ + p];
    float v[2][2][2]; float f0, f1, f2;
    corners(x, c0, c1, c2, v, f0, f1, f2);
    float u00 = v[0][0][0] * (1.f - f2) + v[0][0][1] * f2;
    float u01 = v[0][1][0] * (1.f - f2) + v[0][1][1] * f2;
    float u10 = v[1][0][0] * (1.f - f2) + v[1][0][1] * f2;
    float u11 = v[1][1][0] * (1.f - f2) + v[1][1][1] * f2;
    float t0 = u00 * (1.f - f1) + u01 * f1;
    float t1 = u10 * (1.f - f1) + u11 * f1;
    float Iw = t0 * (1.f - f0) + t1 * f0;
    float yy = y[p];

    __shared__ float s[3][DD + 8];
    s[0][4 + k] = Iw;
    s[1][4 + k] = Iw * Iw;
    s[2][4 + k] = Iw * yy;
    if (k < 4) {
        s[0][k] = 0.f; s[1][k] = 0.f; s[2][k] = 0.f;
        s[0][DD + 4 + k] = 0.f; s[1][DD + 4 + k] = 0.f; s[2][DD + 4 + k] = 0.f;
    }
    __syncthreads();
    float r0 = 0.f, r1 = 0.f, r2 = 0.f;
#pragma unroll
    for (int t = 0; t < 9; t++) {
        r0 += s[0][k + t]; r1 += s[1][k + t]; r2 += s[2][k + t];
    }
    d_A[p] = r0; d_A[NSZ + p] = r1; d_A[2 * NSZ + p] = r2;
}

// D-axis box of (y, y*y) -> d_A[0..1]
__global__ void k_boxd_pre(const float* __restrict__ y)
{
    int line = blockIdx.x;
    int k = threadIdx.x;
    int p = line * DD + k;
    float yy = y[p];
    __shared__ float s[2][DD + 8];
    s[0][4 + k] = yy; s[1][4 + k] = yy * yy;
    if (k < 4) {
        s[0][k] = 0.f; s[1][k] = 0.f;
        s[0][DD + 4 + k] = 0.f; s[1][DD + 4 + k] = 0.f;
    }
    __syncthreads();
    float r0 = 0.f, r1 = 0.f;
#pragma unroll
    for (int t = 0; t < 9; t++) { r0 += s[0][k + t]; r1 += s[1][k + t]; }
    d_A[p] = r0; d_A[NSZ + p] = r1;
}

// ---------------------------------------------------------------------------
// Strided-axis box, ONE FIELD per thread (field = blockIdx.y), sliding window,
// float4 across the contiguous lo dimension.
// ---------------------------------------------------------------------------
__global__ void k_box1(int ssel, int dsel, int L, int S, int nlo4, int nchunk,
                       int total)
{
    int tid = blockIdx.x * 256 + threadIdx.x;
    if (tid >= total) return;
    int f = blockIdx.y;
    int lo4 = tid % nlo4;
    int rest = tid / nlo4;
    int chunk = rest % nchunk;
    int hi = rest / nchunk;

    const float* __restrict__ in = bufsel(ssel) + f * NSZ;
    float* __restrict__ out = bufsel(dsel) + f * NSZ;

    int c0 = chunk * CHUNK;
    int base = hi * L * S + lo4 * 4;

    float4 s = f4z();
#pragma unroll
    for (int t = -4; t <= 4; t++) {
        int a = c0 + t;
        if ((unsigned)a < (unsigned)L)
            s = s + *(const float4*)(in + base + a * S);
    }
    *(float4*)(out + base + c0 * S) = s;

#pragma unroll
    for (int o = 1; o < CHUNK; o++) {
        int a = c0 + o;
        int ain = a + 4, aout = a - 5;
        float4 vin  = ((unsigned)ain < (unsigned)L) ? *(const float4*)(in + base + ain * S)  : f4z();
        float4 vout = (aout >= 0)                   ? *(const float4*)(in + base + aout * S) : f4z();
        s = s + vin - vout;
        *(float4*)(out + base + a * S) = s;
    }
}

// ---------------------------------------------------------------------------
// per-lane NCC partials from full window sums
// ---------------------------------------------------------------------------
__device__ __forceinline__ void gcalc(float SI, float SII, float SIJ,
                                      float SJ, float SJJ,
                                      float& gI, float& gII, float& gIJ)
{
    float uI = SI / WSF, uJ = SJ / WSF;
    float cross = SIJ - uJ * SI - uI * SJ + uI * uJ * WSF;
    float Iv = SII - 2.f * uI * SI + uI * uI * WSF;
    float Jv = SJJ - 2.f * uJ * SJ + uJ * uJ * WSF;
    float Dn = Iv * Jv + 1e-5f;
    float t0 = cross / Dn;
    float q  = 2.f * t0;
    float r  = t0 * t0 * Jv;
    gI  = -q * uJ + 2.f * r * uI;
    gII = -r;
    gIJ = q;
}

// ---------------------------------------------------------------------------
// Forward H-axis box of (S_I,S_II,S_IJ partial sums) fused with gf:
// completes the window sums in registers and emits g-fields directly.
// in: d_Bf (D,W-boxed), d_J (full J sums)  ->  out: d_A = (gI,gII,gIJ)
// CHUNK=8 along H for parallelism.
// ---------------------------------------------------------------------------
__global__ void k_boxh_gf(void)
{
    const int nlo4 = (WW * DD) / 4;   // 7680
    const int nch  = HH / 8;          // 20
    int tid = blockIdx.x * 256 + threadIdx.x;
    if (tid >= nlo4 * nch) return;
    int lo4 = tid % nlo4;
    int chunk = tid / nlo4;
    int c0 = chunk * 8;
    int base = lo4 * 4;
    const int S = WW * DD;

    float4 s0 = f4z(), s1 = f4z(), s2 = f4z();
#pragma unroll
    for (int t = -4; t <= 4; t++) {
        int a = c0 + t;
        if ((unsigned)a < (unsigned)HH) {
            s0 = s0 + *(const float4*)(d_Bf + base + a * S);
            s1 = s1 + *(const float4*)(d_Bf + NSZ + base + a * S);
            s2 = s2 + *(const float4*)(d_Bf + 2 * NSZ + base + a * S);
        }
    }

#pragma unroll
    for (int o = 0; o < 8; o++) {
        int a = c0 + o;
        if (o > 0) {
            int ain = a + 4, aout = a - 5;
            if ((unsigned)ain < (unsigned)HH) {
                s0 = s0 + *(const float4*)(d_Bf + base + ain * S);
                s1 = s1 + *(const float4*)(d_Bf + NSZ + base + ain * S);
                s2 = s2 + *(const float4*)(d_Bf + 2 * NSZ + base + ain * S);
            }
            if (aout >= 0) {
                s0 = s0 - *(const float4*)(d_Bf + base + aout * S);
                s1 = s1 - *(const float4*)(d_Bf + NSZ + base + aout * S);
                s2 = s2 - *(const float4*)(d_Bf + 2 * NSZ + base + aout * S);
            }
        }
        float4 J0 = *(const float4*)(d_J + base + a * S);
        float4 J1 = *(const float4*)(d_J + NSZ + base + a * S);
        float4 o0, o1, o2;
        gcalc(s0.x, s1.x, s2.x, J0.x, J1.x, o0.x, o1.x, o2.x);
        gcalc(s0.y, s1.y, s2.y, J0.y, J1.y, o0.y, o1.y, o2.y);
        gcalc(s0.z, s1.z, s2.z, J0.z, J1.z, o0.z, o1.z, o2.z);
        gcalc(s0.w, s1.w, s2.w, J0.w, J1.w, o0.w, o1.w, o2.w);
        *(float4*)(d_A + base + a * S) = o0;
        *(float4*)(d_A + NSZ + base + a * S) = o1;
        *(float4*)(d_A + 2 * NSZ + base + a * S) = o2;
    }
}

// ---------------------------------------------------------------------------
// chain rule + adjoint D-box (inline 9-tap contiguous window on d_A) +
// reg grad + Adam(amsgrad).  Optionally emits reduction partials (t=5).
// d_A holds box_W(box_H(g*)) fields.
// ---------------------------------------------------------------------------
__global__ void k_chain_adam(const float* __restrict__ x, const float* __restrict__ y,
                             const float* __restrict__ init,
                             int flip, float bc1, float sbc2, int dored)
{
    const float* fc_ = flip ? d_flowB : d_flowA;
    float*       fn_ = flip ? d_flowA : d_flowB;
    int p = blockIdx.x * 256 + threadIdx.x;
    int k = p % DD; int t = p / DD; int j = t % WW; int i = t / WW;

    float f0 = fc_[p], f1 = fc_[NSZ + p], f2c = fc_[2 * NSZ + p];
    float c0 = (float)i + f0, c1 = (float)j + f1, c2 = (float)k + f2c;
    float v[2][2][2]; float fr0, fr1, fr2;
    corners(x, c0, c1, c2, v, fr0, fr1, fr2);
    float u00 = v[0][0][0] * (1.f - fr2) + v[0][0][1] * fr2;
    float u01 = v[0][1][0] * (1.f - fr2) + v[0][1][1] * fr2;
    float u10 = v[1][0][0] * (1.f - fr2) + v[1][0][1] * fr2;
    float u11 = v[1][1][0] * (1.f - fr2) + v[1][1][1] * fr2;
    float ta = u00 * (1.f - fr1) + u01 * fr1;
    float tb = u10 * (1.f - fr1) + u11 * fr1;
    float val = ta * (1.f - fr0) + tb * fr0;                 // Iw
    float gx0 = tb - ta;
    float gx1 = (1.f - fr0) * (u01 - u00) + fr0 * (u11 - u10);
    float d00 = v[0][0][1] - v[0][0][0], d01 = v[0][1][1] - v[0][1][0];
    float d10 = v[1][0][1] - v[1][0][0], d11 = v[1][1][1] - v[1][1][0];
    float gx2 = (1.f - fr0) * ((1.f - fr1) * d00 + fr1 * d01)
              + fr0 * ((1.f - fr1) * d10 + fr1 * d11);

    // adjoint D-box inline: 9-tap contiguous window (zero pad)
    float b0 = 0.f, b1 = 0.f, b2 = 0.f;
#pragma unroll
    for (int tt = -4; tt <= 4; tt++) {
        int kk = k + tt;
        if ((unsigned)kk < (unsigned)DD) {
            b0 += d_A[p + tt];
            b1 += d_A[NSZ + p + tt];
            b2 += d_A[2 * NSZ + p + tt];
        }
    }
    float dI = -INVN * (b0 + 2.f * val * b1 + y[p] * b2);

    float gx[3]  = {gx0, gx1, gx2};
    float fcv[3] = {f0, f1, f2c};
    double acc = 0.0;
#pragma unroll
    for (int ch = 0; ch < 3; ch++) {
        int e = ch * NSZ + p;
        float fcc = fcv[ch];
        float reg = 0.f;
        if (i > 0)      reg += CH_ * (fcc - fc_[e - WW * DD]);
        if (i < HH - 1) reg -= CH_ * (fc_[e + WW * DD] - fcc);
        if (j > 0)      reg += CW_ * (fcc - fc_[e - DD]);
        if (j < WW - 1) reg -= CW_ * (fc_[e + DD] - fcc);
        if (k > 0)      reg += CD_ * (fcc - fc_[e - 1]);
        if (k < DD - 1) reg -= CD_ * (fc_[e + 1] - fcc);
        float g = dI * gx[ch] + reg;

        float mm = 0.9f * d_m[e] + 0.1f * g;
        float vv = 0.999f * d_v[e] + 0.001f * g * g;
        float vh = fmaxf(d_vh[e], vv);
        d_m[e] = mm; d_v[e] = vv; d_vh[e] = vh;
        float denom = sqrtf(vh) / sbc2 + 1e-8f;
        float fnew = fcc - 0.1f * (mm / bc1) / denom;
        fn_[e] = fnew;
        if (dored) {
            float d = fnew - init[e];
            acc += (double)(d * d);
        }
    }

    if (dored) {
        __shared__ double sd[256];
        sd[threadIdx.x] = acc; __syncthreads();
        for (int s = 128; s > 0; s >>= 1) {
            if (threadIdx.x < s) sd[threadIdx.x] += sd[threadIdx.x + s];
            __syncthreads();
        }
        if (threadIdx.x == 0) d_part[blockIdx.x] = sd[0];
    }
}

// ---------------------------------------------------------------------------
__global__ void k_red2(float* __restrict__ out)
{
    double acc = 0.0;
    for (int e = threadIdx.x; e < NBCHAIN; e += 1024) acc += d_part[e];
    __shared__ double sd[1024];
    sd[threadIdx.x] = acc; __syncthreads();
    for (int s = 512; s > 0; s >>= 1) {
        if (threadIdx.x < s) sd[threadIdx.x] += sd[threadIdx.x + s];
        __syncthreads();
    }
    if (threadIdx.x == 0) out[0] = (float)(sd[0] / (double)N3);
}

// ---------------------------------------------------------------------------
extern "C" void kernel_launch(void* const* d_in, const int* in_sizes, int n_in,
                              void* d_out, int out_size)
{
    (void)in_sizes; (void)n_in; (void)out_size;
    const float* x    = (const float*)d_in[0];
    const float* y    = (const float*)d_in[1];
    const float* init = (const float*)d_in[2];
    float* out = (float*)d_out;

    // W-axis pass params: L=WW, S=DD, nlo4=DD/4, nchunk=WW/CHUNK
    const int W_L = WW, W_S = DD, W_nlo4 = DD / 4, W_nch = WW / CHUNK;
    const int W_total = W_nlo4 * W_nch * HH;          // 76800 per field
    // H-axis pass params: L=HH, S=WW*DD, nlo4=(WW*DD)/4, nchunk=HH/CHUNK
    const int H_L = HH, H_S = WW * DD, H_nlo4 = (WW * DD) / 4, H_nch = HH / CHUNK;
    const int H_total = H_nlo4 * H_nch;               // 76800 per field
    const int BOX_BLOCKS = (W_total + 255) / 256;     // 300

    k_init<<<N3 / 256, 256>>>(init);

    // precompute S_J, S_JJ: boxD -> boxW -> boxH into d_J (2 fields)
    k_boxd_pre<<<HH * WW, DD>>>(y);
    k_box1<<<dim3(BOX_BLOCKS, 2), 256>>>(0, 1, W_L, W_S, W_nlo4, W_nch, W_total);
    k_box1<<<dim3(BOX_BLOCKS, 2), 256>>>(1, 2, H_L, H_S, H_nlo4, H_nch, H_total);

    for (int t = 1; t <= 5; t++) {
        int flip = (t - 1) & 1;
        float bc1  = (float)(1.0 - pow(0.9, (double)t));
        float sbc2 = sqrtf((float)(1.0 - pow(0.999, (double)t)));

        // forward: warp + D-box (fused), W-box, H-box fused with gf
        k_boxd_fwd<<<HH * WW, DD>>>(x, y, flip);
        k_box1<<<dim3(BOX_BLOCKS, 3), 256>>>(0, 1, W_L, W_S, W_nlo4, W_nch, W_total); // A->Bf
        k_boxh_gf<<<600, 256>>>();                                                    // Bf,J->A (g)
        // adjoint: H-box, W-box (D-box fused into chain)
        k_box1<<<dim3(BOX_BLOCKS, 3), 256>>>(0, 1, H_L, H_S, H_nlo4, H_nch, H_total); // A->Bf
        k_box1<<<dim3(BOX_BLOCKS, 3), 256>>>(1, 0, W_L, W_S, W_nlo4, W_nch, W_total); // Bf->A
        // chain rule + inline adjoint D-box + reg grad + Adam (+partials at t=5)
        k_chain_adam<<<NBCHAIN, 256>>>(x, y, init, flip, bc1, sbc2, t == 5 ? 1 : 0);
    }

    k_red2<<<1, 1024>>>(out);
}